// round 5
// baseline (speedup 1.0000x reference)
#include <cuda_runtime.h>
#include <cuda_bf16.h>
#include <cstdint>
#include <cstddef>

#define DI __device__ __forceinline__

// ---------------- problem constants ----------------
constexpr int Hdim = 1024;
constexpr int NH   = 16;
constexpr int KS   = 31;
constexpr int Bn   = 4;
constexpr int Sn   = 4096;
constexpr int Mrows = Bn * Sn;          // 16384
constexpr float EPSLN = 1e-5f;

// ---------------- scratch (device globals; no allocation allowed) ----------------
__device__ __align__(4096) __nv_bfloat16 g_Xhi[(size_t)Mrows * Hdim];
__device__ __align__(4096) __nv_bfloat16 g_Xlo[(size_t)Mrows * Hdim];
__device__ __align__(4096) __nv_bfloat16 g_Chi[(size_t)Mrows * Hdim];
__device__ __align__(4096) __nv_bfloat16 g_Clo[(size_t)Mrows * Hdim];
__device__ __align__(4096) __nv_bfloat16 g_WinHi[(size_t)Hdim * Hdim];
__device__ __align__(4096) __nv_bfloat16 g_WinLo[(size_t)Hdim * Hdim];
__device__ __align__(4096) __nv_bfloat16 g_WoutHi[(size_t)Hdim * Hdim];
__device__ __align__(4096) __nv_bfloat16 g_WoutLo[(size_t)Hdim * Hdim];
__device__ __align__(4096) float g_Y1[(size_t)Mrows * Hdim];
__device__ __align__(4096) float g_Y2[(size_t)Mrows * Hdim];
__device__ __align__(4096) float g_Wc[NH * KS];

// ---------------- PTX helpers (sm_100 baseline only: no tcgen05/TMEM) ----------------
DI uint32_t smem_u32(const void* p) {
    uint32_t a;
    asm("{ .reg .u64 t; cvta.to.shared.u64 t, %1; cvt.u32.u64 %0, t; }" : "=r"(a) : "l"(p));
    return a;
}
DI void cp16(uint32_t dst, const void* src) {
    asm volatile("cp.async.cg.shared.global [%0], [%1], 16;" :: "r"(dst), "l"(src) : "memory");
}
DI void cp_commit() { asm volatile("cp.async.commit_group;" ::: "memory"); }
template<int N> DI void cp_waitg() { asm volatile("cp.async.wait_group %0;" :: "n"(N) : "memory"); }
DI void ldm4(uint32_t* r, uint32_t a) {
    asm volatile("ldmatrix.sync.aligned.m8n8.x4.shared.b16 {%0,%1,%2,%3}, [%4];"
                 : "=r"(r[0]), "=r"(r[1]), "=r"(r[2]), "=r"(r[3]) : "r"(a));
}
DI void mma16816(float* d, const uint32_t* a, const uint32_t* b) {
    asm volatile(
        "mma.sync.aligned.m16n8k16.row.col.f32.bf16.bf16.f32 "
        "{%0,%1,%2,%3}, {%4,%5,%6,%7}, {%8,%9}, {%0,%1,%2,%3};"
        : "+f"(d[0]), "+f"(d[1]), "+f"(d[2]), "+f"(d[3])
        : "r"(a[0]), "r"(a[1]), "r"(a[2]), "r"(a[3]), "r"(b[0]), "r"(b[1]));
}

// ---------------- GEMM: D[M,N] = A[M,K] @ W[N,K]^T, split-bf16 x3 ----------------
// CTA tile 128x128, K-chunk 32, 256 threads (8 warps: 2 M x 4 N, warp tile 64x32).
// smem rows padded to 80B -> (row*5 + chunk) mod 8 is a permutation over any 8
// consecutive rows: conflict-free ldmatrix with no swizzle.
constexpr int KC = 32;
constexpr int NCH = Hdim / KC;          // 32
constexpr int ROWB = 80;                // 64B data + 16B pad
constexpr int TILEB = 128 * ROWB;       // 10240 B per matrix tile
constexpr int STG = 4 * TILEB;          // AHI, ALO, BHI, BLO = 40960 B / stage
constexpr int NSTAGE = 3;
constexpr int SMEM_GEMM = NSTAGE * STG; // 122880 B

__global__ void __launch_bounds__(256, 1) gemm_bf16x3(
    const __nv_bfloat16* __restrict__ Ahi, const __nv_bfloat16* __restrict__ Alo,
    const __nv_bfloat16* __restrict__ Bhi, const __nv_bfloat16* __restrict__ Blo,
    const float* __restrict__ bias, const float* __restrict__ residual,
    float* __restrict__ out)
{
    extern __shared__ char smem[];
    const uint32_t sb = smem_u32(smem);
    const int tid = threadIdx.x, lane = tid & 31, wid = tid >> 5;
    const int wm = wid >> 2, wn = wid & 3;
    const int m0 = blockIdx.y * 128, n0 = blockIdx.x * 128;
    const int lrow = tid >> 2, lch = tid & 3;

    auto issue = [&](int c) {
        const uint32_t st = sb + (uint32_t)(c % NSTAGE) * STG;
        #pragma unroll
        for (int i = 0; i < 2; i++) {
            const int row = i * 64 + lrow;
            const size_t goA = (size_t)(m0 + row) * Hdim + c * KC + lch * 8;
            const size_t goB = (size_t)(n0 + row) * Hdim + c * KC + lch * 8;
            const uint32_t so = (uint32_t)(row * ROWB + lch * 16);
            cp16(st + so,             Ahi + goA);
            cp16(st + TILEB + so,     Alo + goA);
            cp16(st + 2 * TILEB + so, Bhi + goB);
            cp16(st + 3 * TILEB + so, Blo + goB);
        }
    };

    issue(0); cp_commit();
    issue(1); cp_commit();

    float acc[4][4][4];
    #pragma unroll
    for (int a = 0; a < 4; a++)
        #pragma unroll
        for (int b = 0; b < 4; b++)
            #pragma unroll
            for (int d = 0; d < 4; d++) acc[a][b][d] = 0.f;

    const int ti = lane >> 3, lr = lane & 7;

    for (int c = 0; c < NCH; c++) {
        cp_waitg<NSTAGE - 2>();
        __syncthreads();
        const uint32_t st = sb + (uint32_t)(c % NSTAGE) * STG;
        #pragma unroll
        for (int ks = 0; ks < 2; ks++) {
            uint32_t aH[4][4], aL[4][4], bH[4][2], bL[4][2];
            // A fragments: x4 tiles = (rows+0,ch0)(rows+8,ch0)(rows+0,ch1)(rows+8,ch1)
            #pragma unroll
            for (int mt = 0; mt < 4; mt++) {
                const int row = wm * 64 + mt * 16 + lr + (ti & 1) * 8;
                const int ch = 2 * ks + (ti >> 1);
                const uint32_t ad = st + (uint32_t)(row * ROWB + ch * 16);
                ldm4(aH[mt], ad);
                ldm4(aL[mt], ad + TILEB);
            }
            // B fragments: x4 tiles = b0(nt),b1(nt),b0(nt+1),b1(nt+1)
            #pragma unroll
            for (int np = 0; np < 2; np++) {
                const int row = wn * 32 + np * 16 + lr + (ti >> 1) * 8;
                const int ch = 2 * ks + (ti & 1);
                const uint32_t bd = st + 2 * TILEB + (uint32_t)(row * ROWB + ch * 16);
                uint32_t q[4];
                ldm4(q, bd);
                bH[np * 2][0] = q[0]; bH[np * 2][1] = q[1];
                bH[np * 2 + 1][0] = q[2]; bH[np * 2 + 1][1] = q[3];
                ldm4(q, bd + TILEB);
                bL[np * 2][0] = q[0]; bL[np * 2][1] = q[1];
                bL[np * 2 + 1][0] = q[2]; bL[np * 2 + 1][1] = q[3];
            }
            // 3-term split-bf16 product
            #pragma unroll
            for (int mt = 0; mt < 4; mt++)
                #pragma unroll
                for (int nt = 0; nt < 4; nt++) {
                    mma16816(acc[mt][nt], aH[mt], bH[nt]);
                    mma16816(acc[mt][nt], aH[mt], bL[nt]);
                    mma16816(acc[mt][nt], aL[mt], bH[nt]);
                }
        }
        __syncthreads();
        if (c + NSTAGE - 1 < NCH) issue(c + NSTAGE - 1);
        cp_commit();
    }

    // epilogue: d0,d1 -> (row g, col 2t..2t+1); d2,d3 -> row g+8
    const int g = lane >> 2, t4 = lane & 3;
    #pragma unroll
    for (int mt = 0; mt < 4; mt++) {
        #pragma unroll
        for (int nt = 0; nt < 4; nt++) {
            const int row = m0 + wm * 64 + mt * 16 + g;
            const int col = n0 + wn * 32 + nt * 8 + 2 * t4;
            const float2 bi = *(const float2*)(bias + col);
            float* d = acc[mt][nt];
            float2 v0 = make_float2(d[0] + bi.x, d[1] + bi.y);
            float2 v1 = make_float2(d[2] + bi.x, d[3] + bi.y);
            if (residual) {
                const float2 r0 = *(const float2*)(residual + (size_t)row * Hdim + col);
                const float2 r1 = *(const float2*)(residual + (size_t)(row + 8) * Hdim + col);
                v0.x += r0.x; v0.y += r0.y;
                v1.x += r1.x; v1.y += r1.y;
            }
            *(float2*)(out + (size_t)row * Hdim + col) = v0;
            *(float2*)(out + (size_t)(row + 8) * Hdim + col) = v1;
        }
    }
}

// ---------------- fp32 -> (bf16 hi, bf16 lo) split ----------------
DI void split1(float x, uint16_t& h, uint16_t& l) {
    __nv_bfloat16 hb = __float2bfloat16(x);
    __nv_bfloat16 lb = __float2bfloat16(x - __bfloat162float(hb));
    h = __bfloat16_as_ushort(hb);
    l = __bfloat16_as_ushort(lb);
}
__global__ void split_bf16_kernel(const float4* __restrict__ src,
                                  uint2* __restrict__ hi, uint2* __restrict__ lo, int n4)
{
    for (int i = blockIdx.x * blockDim.x + threadIdx.x; i < n4; i += gridDim.x * blockDim.x) {
        float4 v = src[i];
        uint16_t h0, h1, h2, h3, l0, l1, l2, l3;
        split1(v.x, h0, l0); split1(v.y, h1, l1);
        split1(v.z, h2, l2); split1(v.w, h3, l3);
        hi[i] = make_uint2((uint32_t)h0 | ((uint32_t)h1 << 16),
                           (uint32_t)h2 | ((uint32_t)h3 << 16));
        lo[i] = make_uint2((uint32_t)l0 | ((uint32_t)l1 << 16),
                           (uint32_t)l2 | ((uint32_t)l3 << 16));
    }
}

// ---------------- conv weight prep: softmax over K, then causal mask ----------------
__global__ void convw_kernel(const float* __restrict__ cw, const int* __restrict__ maskp,
                             int has_mask, float* __restrict__ wc)
{
    int h = threadIdx.x;
    if (h >= NH) return;
    bool masked = has_mask ? (maskp[0] != 0) : true;
    float m = -1e30f;
    for (int k = 0; k < KS; k++) m = fmaxf(m, cw[h * KS + k]);
    float e[KS]; float s = 0.f;
    for (int k = 0; k < KS; k++) { e[k] = expf(cw[h * KS + k] - m); s += e[k]; }
    float inv = 1.f / s;
    for (int k = 0; k < KS; k++) {
        float w = e[k] * inv;
        if (masked && k >= (KS / 2 + 1)) w = 0.f;   // pivot = 16: keep taps 0..15
        wc[h * KS + k] = w;
    }
}

// ---------------- depthwise conv along S; head = h % 16; zero padding 15 each side ----------
__global__ void __launch_bounds__(256) conv_kernel(
    const float* __restrict__ Y1, const float* __restrict__ wc,
    __nv_bfloat16* __restrict__ chi, __nv_bfloat16* __restrict__ clo)
{
    __shared__ float tile[(128 + 30) * 64];
    __shared__ float ws[NH * KS];
    const int b = blockIdx.z, s0 = blockIdx.y * 128, h0 = blockIdx.x * 64;
    const int tid = threadIdx.x;
    for (int i = tid; i < NH * KS; i += 256) ws[i] = wc[i];
    for (int i = tid; i < 158 * 64; i += 256) {
        int r = i >> 6, c = i & 63;
        int s = s0 - 15 + r;
        float v = 0.f;
        if (s >= 0 && s < Sn) v = Y1[(size_t)(b * Sn + s) * Hdim + h0 + c];
        tile[i] = v;
    }
    __syncthreads();
    const int c = tid & 63;
    const int sset = tid >> 6;
    float w[KS];
    #pragma unroll
    for (int t = 0; t < KS; t++) w[t] = ws[(c & 15) * KS + t];
    for (int i = 0; i < 4; i++) {
        const int r0 = (sset + 4 * i) * 8;
        float acc[8] = {0, 0, 0, 0, 0, 0, 0, 0};
        #pragma unroll
        for (int rr = 0; rr < 38; rr++) {
            float x = tile[(r0 + rr) * 64 + c];
            #pragma unroll
            for (int o = 0; o < 8; o++) {
                int t = rr - o;
                if (t >= 0 && t <= 30) acc[o] += w[t] * x;
            }
        }
        #pragma unroll
        for (int o = 0; o < 8; o++) {
            int s = s0 + r0 + o;
            size_t idx = (size_t)(b * Sn + s) * Hdim + h0 + c;
            float v = acc[o];
            __nv_bfloat16 hb = __float2bfloat16(v);
            __nv_bfloat16 lb = __float2bfloat16(v - __bfloat162float(hb));
            chi[idx] = hb; clo[idx] = lb;
        }
    }
}

// ---------------- LayerNorm over H per row ----------------
__global__ void __launch_bounds__(256) ln_kernel(
    const float* __restrict__ Y, const float* __restrict__ gamma,
    const float* __restrict__ beta, float* __restrict__ out)
{
    const int row = blockIdx.x, tid = threadIdx.x;
    const float4* yr = (const float4*)(Y + (size_t)row * Hdim);
    float4 v = yr[tid];
    float s = v.x + v.y + v.z + v.w;
    float ss = v.x * v.x + v.y * v.y + v.z * v.z + v.w * v.w;
    #pragma unroll
    for (int o = 16; o > 0; o >>= 1) {
        s  += __shfl_xor_sync(0xffffffffu, s,  o);
        ss += __shfl_xor_sync(0xffffffffu, ss, o);
    }
    __shared__ float rs[8], rss[8];
    __shared__ float s_mu, s_inv;
    if ((tid & 31) == 0) { rs[tid >> 5] = s; rss[tid >> 5] = ss; }
    __syncthreads();
    if (tid == 0) {
        float S = 0, SS = 0;
        #pragma unroll
        for (int i = 0; i < 8; i++) { S += rs[i]; SS += rss[i]; }
        float mu = S * (1.f / Hdim);
        float var = SS * (1.f / Hdim) - mu * mu;
        s_mu = mu; s_inv = rsqrtf(var + EPSLN);
    }
    __syncthreads();
    float4 g = ((const float4*)gamma)[tid];
    float4 bb = ((const float4*)beta)[tid];
    float mu = s_mu, inv = s_inv;
    float4 o4;
    o4.x = (v.x - mu) * inv * g.x + bb.x;
    o4.y = (v.y - mu) * inv * g.y + bb.y;
    o4.z = (v.z - mu) * inv * g.z + bb.z;
    o4.w = (v.w - mu) * inv * g.w + bb.w;
    ((float4*)(out + (size_t)row * Hdim))[tid] = o4;
}

// ---------------- launch ----------------
extern "C" void kernel_launch(void* const* d_in, const int* in_sizes, int n_in,
                              void* d_out, int out_size)
{
    const float* hs     = (const float*)d_in[0];
    const float* W_in   = (const float*)d_in[1];
    const float* b_in   = (const float*)d_in[2];
    const float* conv_w = (const float*)d_in[3];
    const float* W_out  = (const float*)d_in[4];
    const float* b_out  = (const float*)d_in[5];
    const float* gamma  = (const float*)d_in[6];
    const float* beta   = (const float*)d_in[7];
    const int* maskp    = (n_in > 8) ? (const int*)d_in[8] : nullptr;
    float* out = (float*)d_out;

    void *xhi, *xlo, *chi, *clo, *wih, *wil, *woh, *wol, *y1, *y2, *wc;
    cudaGetSymbolAddress(&xhi, g_Xhi);   cudaGetSymbolAddress(&xlo, g_Xlo);
    cudaGetSymbolAddress(&chi, g_Chi);   cudaGetSymbolAddress(&clo, g_Clo);
    cudaGetSymbolAddress(&wih, g_WinHi); cudaGetSymbolAddress(&wil, g_WinLo);
    cudaGetSymbolAddress(&woh, g_WoutHi); cudaGetSymbolAddress(&wol, g_WoutLo);
    cudaGetSymbolAddress(&y1, g_Y1);     cudaGetSymbolAddress(&y2, g_Y2);
    cudaGetSymbolAddress(&wc, g_Wc);

    cudaFuncSetAttribute(gemm_bf16x3, cudaFuncAttributeMaxDynamicSharedMemorySize, SMEM_GEMM);

    const int nAct4 = Mrows * Hdim / 4;   // 4,194,304
    const int nW4   = Hdim * Hdim / 4;    // 262,144
    split_bf16_kernel<<<4096, 256>>>((const float4*)hs, (uint2*)xhi, (uint2*)xlo, nAct4);
    split_bf16_kernel<<<512, 256>>>((const float4*)W_in, (uint2*)wih, (uint2*)wil, nW4);
    split_bf16_kernel<<<512, 256>>>((const float4*)W_out, (uint2*)woh, (uint2*)wol, nW4);
    convw_kernel<<<1, NH>>>(conv_w, maskp, maskp ? 1 : 0, (float*)wc);

    dim3 ggrid(Hdim / 128, Mrows / 128);   // (8, 128)
    gemm_bf16x3<<<ggrid, 256, SMEM_GEMM>>>(
        (const __nv_bfloat16*)xhi, (const __nv_bfloat16*)xlo,
        (const __nv_bfloat16*)wih, (const __nv_bfloat16*)wil,
        b_in, nullptr, (float*)y1);

    conv_kernel<<<dim3(Hdim / 64, Sn / 128, Bn), 256>>>(
        (const float*)y1, (const float*)wc, (__nv_bfloat16*)chi, (__nv_bfloat16*)clo);

    gemm_bf16x3<<<ggrid, 256, SMEM_GEMM>>>(
        (const __nv_bfloat16*)chi, (const __nv_bfloat16*)clo,
        (const __nv_bfloat16*)woh, (const __nv_bfloat16*)wol,
        b_out, hs, (float*)y2);

    ln_kernel<<<Mrows, 256>>>((const float*)y2, gamma, beta, out);
}

// round 6
// speedup vs baseline: 1.2653x; 1.2653x over previous
#include <cuda_runtime.h>
#include <cuda_bf16.h>
#include <cstdint>
#include <cstddef>

#define DI __device__ __forceinline__

// ---------------- problem constants ----------------
constexpr int Hdim = 1024;
constexpr int NH   = 16;
constexpr int KS   = 31;
constexpr int Bn   = 4;
constexpr int Sn   = 4096;
constexpr int Mrows = Bn * Sn;          // 16384
constexpr float EPSLN = 1e-5f;

// ---------------- scratch (device globals; no allocation allowed) ----------------
__device__ __align__(4096) float g_X[(size_t)Mrows * Hdim];     // tf32-rounded hs
__device__ __align__(4096) float g_C[(size_t)Mrows * Hdim];     // tf32-rounded conv out
__device__ __align__(4096) float g_Win[(size_t)Hdim * Hdim];    // tf32-rounded W_in
__device__ __align__(4096) float g_Wout[(size_t)Hdim * Hdim];   // tf32-rounded W_out
__device__ __align__(4096) float g_Y1[(size_t)Mrows * Hdim];
__device__ __align__(4096) float g_Y2[(size_t)Mrows * Hdim];
__device__ __align__(4096) float g_Wc[NH * KS];

// ---------------- PTX helpers (sm_100 baseline only) ----------------
DI uint32_t smem_u32(const void* p) {
    uint32_t a;
    asm("{ .reg .u64 t; cvta.to.shared.u64 t, %1; cvt.u32.u64 %0, t; }" : "=r"(a) : "l"(p));
    return a;
}
DI void cp16(uint32_t dst, const void* src) {
    asm volatile("cp.async.cg.shared.global [%0], [%1], 16;" :: "r"(dst), "l"(src) : "memory");
}
DI void cp_commit() { asm volatile("cp.async.commit_group;" ::: "memory"); }
template<int N> DI void cp_waitg() { asm volatile("cp.async.wait_group %0;" :: "n"(N) : "memory"); }
DI uint32_t tf32_rna(float x) {
    uint32_t t;
    asm("cvt.rna.tf32.f32 %0, %1;" : "=r"(t) : "f"(x));
    return t;
}
DI void mma1688(float* d, const uint32_t* a, const uint32_t* b) {
    asm volatile(
        "mma.sync.aligned.m16n8k8.row.col.f32.tf32.tf32.f32 "
        "{%0,%1,%2,%3}, {%4,%5,%6,%7}, {%8,%9}, {%0,%1,%2,%3};"
        : "+f"(d[0]), "+f"(d[1]), "+f"(d[2]), "+f"(d[3])
        : "r"(a[0]), "r"(a[1]), "r"(a[2]), "r"(a[3]), "r"(b[0]), "r"(b[1]));
}

// ---------------- GEMM: D[M,N] = A[M,K] @ W[N,K]^T, single-pass TF32 ----------------
// CTA tile 128x128, K-chunk 32 (fp32/tf32), 256 threads (8 warps: 2 M x 4 N,
// warp tile 64x32, 4 k-steps of k8 per chunk).
// smem rows padded to 144B (128B data + 16B): row stride = 36 words, so banks
// for fragment loads are (4*g + tg) mod 32 -> all 32 lanes distinct. Conflict-free.
constexpr int KC = 32;
constexpr int NCH = Hdim / KC;          // 32
constexpr int ROWB = 144;
constexpr int TILEB = 128 * ROWB;       // 18432 B
constexpr int STG = 2 * TILEB;          // A + B = 36864 B / stage
constexpr int NSTAGE = 4;
constexpr int SMEM_GEMM = NSTAGE * STG; // 147456 B

__global__ void __launch_bounds__(256, 1) gemm_tf32(
    const float* __restrict__ A, const float* __restrict__ W,
    const float* __restrict__ bias, const float* __restrict__ residual,
    float* __restrict__ out)
{
    extern __shared__ char smem[];
    const uint32_t sb = smem_u32(smem);
    const int tid = threadIdx.x, lane = tid & 31, wid = tid >> 5;
    const int wm = wid >> 2, wn = wid & 3;
    const int m0 = blockIdx.y * 128, n0 = blockIdx.x * 128;

    auto issue = [&](int c) {
        const uint32_t st = sb + (uint32_t)(c % NSTAGE) * STG;
        const int ch = tid & 7;             // 8 x 16B = 128B row
        #pragma unroll
        for (int i = 0; i < 4; i++) {
            const int row = (tid >> 3) + 32 * i;
            const size_t goA = (size_t)(m0 + row) * Hdim + c * KC + ch * 4;
            const size_t goB = (size_t)(n0 + row) * Hdim + c * KC + ch * 4;
            const uint32_t so = (uint32_t)(row * ROWB + ch * 16);
            cp16(st + so,         A + goA);
            cp16(st + TILEB + so, W + goB);
        }
    };

    issue(0); cp_commit();
    issue(1); cp_commit();
    issue(2); cp_commit();

    float acc[4][4][4];
    #pragma unroll
    for (int a = 0; a < 4; a++)
        #pragma unroll
        for (int b = 0; b < 4; b++)
            #pragma unroll
            for (int d = 0; d < 4; d++) acc[a][b][d] = 0.f;

    const int g8 = lane >> 2, tg = lane & 3;

    for (int c = 0; c < NCH; c++) {
        cp_waitg<NSTAGE - 2>();
        __syncthreads();
        const char* st = smem + (size_t)(c % NSTAGE) * STG;
        #pragma unroll
        for (int ks = 0; ks < 4; ks++) {
            const int k0 = ks * 8;
            uint32_t af[4][4], bf[4][2];
            // A fragments (m16k8 per mt): a0=(g,tg) a1=(g+8,tg) a2=(g,tg+4) a3=(g+8,tg+4)
            #pragma unroll
            for (int mt = 0; mt < 4; mt++) {
                const int row0 = wm * 64 + mt * 16 + g8;
                const uint32_t* p = (const uint32_t*)(st + (size_t)row0 * ROWB + (k0 + tg) * 4);
                af[mt][0] = p[0];
                af[mt][1] = *(const uint32_t*)((const char*)p + 8 * ROWB);
                af[mt][2] = p[4];
                af[mt][3] = *(const uint32_t*)((const char*)p + 8 * ROWB + 16);
            }
            // B fragments (k8n8 per nt): b0=B[n=col0+g][k=k0+tg], b1=k+4
            #pragma unroll
            for (int nt = 0; nt < 4; nt++) {
                const int nrow = wn * 32 + nt * 8 + g8;
                const uint32_t* p = (const uint32_t*)(st + TILEB + (size_t)nrow * ROWB + (k0 + tg) * 4);
                bf[nt][0] = p[0];
                bf[nt][1] = p[4];
            }
            #pragma unroll
            for (int mt = 0; mt < 4; mt++)
                #pragma unroll
                for (int nt = 0; nt < 4; nt++)
                    mma1688(acc[mt][nt], af[mt], bf[nt]);
        }
        __syncthreads();
        if (c + NSTAGE - 1 < NCH) issue(c + NSTAGE - 1);
        cp_commit();
    }

    // epilogue: d0,d1 -> (row g, col 2t,2t+1); d2,d3 -> row g+8
    const int g = lane >> 2, t4 = lane & 3;
    #pragma unroll
    for (int mt = 0; mt < 4; mt++) {
        #pragma unroll
        for (int nt = 0; nt < 4; nt++) {
            const int row = m0 + wm * 64 + mt * 16 + g;
            const int col = n0 + wn * 32 + nt * 8 + 2 * t4;
            const float2 bi = *(const float2*)(bias + col);
            float* d = acc[mt][nt];
            float2 v0 = make_float2(d[0] + bi.x, d[1] + bi.y);
            float2 v1 = make_float2(d[2] + bi.x, d[3] + bi.y);
            if (residual) {
                const float2 r0 = *(const float2*)(residual + (size_t)row * Hdim + col);
                const float2 r1 = *(const float2*)(residual + (size_t)(row + 8) * Hdim + col);
                v0.x += r0.x; v0.y += r0.y;
                v1.x += r1.x; v1.y += r1.y;
            }
            *(float2*)(out + (size_t)row * Hdim + col) = v0;
            *(float2*)(out + (size_t)(row + 8) * Hdim + col) = v1;
        }
    }
}

// ---------------- fp32 -> tf32-rounded fp32 (RN — truncation would bias!) ----------------
__global__ void round_tf32_kernel(const float4* __restrict__ src, uint4* __restrict__ dst, int n4)
{
    for (int i = blockIdx.x * blockDim.x + threadIdx.x; i < n4; i += gridDim.x * blockDim.x) {
        float4 v = src[i];
        dst[i] = make_uint4(tf32_rna(v.x), tf32_rna(v.y), tf32_rna(v.z), tf32_rna(v.w));
    }
}

// ---------------- conv weight prep: softmax over K, then causal mask ----------------
__global__ void convw_kernel(const float* __restrict__ cw, const int* __restrict__ maskp,
                             int has_mask, float* __restrict__ wc)
{
    int h = threadIdx.x;
    if (h >= NH) return;
    bool masked = has_mask ? (maskp[0] != 0) : true;
    float m = -1e30f;
    for (int k = 0; k < KS; k++) m = fmaxf(m, cw[h * KS + k]);
    float e[KS]; float s = 0.f;
    for (int k = 0; k < KS; k++) { e[k] = expf(cw[h * KS + k] - m); s += e[k]; }
    float inv = 1.f / s;
    for (int k = 0; k < KS; k++) {
        float w = e[k] * inv;
        if (masked && k >= (KS / 2 + 1)) w = 0.f;   // pivot = 16: keep taps 0..15
        wc[h * KS + k] = w;
    }
}

// ---------------- depthwise conv along S; head = h % 16; zero padding 15 each side ----------
__global__ void __launch_bounds__(256) conv_kernel(
    const float* __restrict__ Y1, const float* __restrict__ wc,
    float* __restrict__ Cout)
{
    __shared__ float tile[(128 + 30) * 64];
    __shared__ float ws[NH * KS];
    const int b = blockIdx.z, s0 = blockIdx.y * 128, h0 = blockIdx.x * 64;
    const int tid = threadIdx.x;
    for (int i = tid; i < NH * KS; i += 256) ws[i] = wc[i];
    for (int i = tid; i < 158 * 64; i += 256) {
        int r = i >> 6, c = i & 63;
        int s = s0 - 15 + r;
        float v = 0.f;
        if (s >= 0 && s < Sn) v = Y1[(size_t)(b * Sn + s) * Hdim + h0 + c];
        tile[i] = v;
    }
    __syncthreads();
    const int c = tid & 63;
    const int sset = tid >> 6;
    float w[KS];
    #pragma unroll
    for (int t = 0; t < KS; t++) w[t] = ws[(c & 15) * KS + t];
    for (int i = 0; i < 4; i++) {
        const int r0 = (sset + 4 * i) * 8;
        float acc[8] = {0, 0, 0, 0, 0, 0, 0, 0};
        #pragma unroll
        for (int rr = 0; rr < 38; rr++) {
            float x = tile[(r0 + rr) * 64 + c];
            #pragma unroll
            for (int o = 0; o < 8; o++) {
                int t = rr - o;
                if (t >= 0 && t <= 30) acc[o] += w[t] * x;
            }
        }
        #pragma unroll
        for (int o = 0; o < 8; o++) {
            int s = s0 + r0 + o;
            size_t idx = (size_t)(b * Sn + s) * Hdim + h0 + c;
            ((uint32_t*)Cout)[idx] = tf32_rna(acc[o]);
        }
    }
}

// ---------------- LayerNorm over H per row ----------------
__global__ void __launch_bounds__(256) ln_kernel(
    const float* __restrict__ Y, const float* __restrict__ gamma,
    const float* __restrict__ beta, float* __restrict__ out)
{
    const int row = blockIdx.x, tid = threadIdx.x;
    const float4* yr = (const float4*)(Y + (size_t)row * Hdim);
    float4 v = yr[tid];
    float s = v.x + v.y + v.z + v.w;
    float ss = v.x * v.x + v.y * v.y + v.z * v.z + v.w * v.w;
    #pragma unroll
    for (int o = 16; o > 0; o >>= 1) {
        s  += __shfl_xor_sync(0xffffffffu, s,  o);
        ss += __shfl_xor_sync(0xffffffffu, ss, o);
    }
    __shared__ float rs[8], rss[8];
    __shared__ float s_mu, s_inv;
    if ((tid & 31) == 0) { rs[tid >> 5] = s; rss[tid >> 5] = ss; }
    __syncthreads();
    if (tid == 0) {
        float S = 0, SS = 0;
        #pragma unroll
        for (int i = 0; i < 8; i++) { S += rs[i]; SS += rss[i]; }
        float mu = S * (1.f / Hdim);
        float var = SS * (1.f / Hdim) - mu * mu;
        s_mu = mu; s_inv = rsqrtf(var + EPSLN);
    }
    __syncthreads();
    float4 g = ((const float4*)gamma)[tid];
    float4 bb = ((const float4*)beta)[tid];
    float mu = s_mu, inv = s_inv;
    float4 o4;
    o4.x = (v.x - mu) * inv * g.x + bb.x;
    o4.y = (v.y - mu) * inv * g.y + bb.y;
    o4.z = (v.z - mu) * inv * g.z + bb.z;
    o4.w = (v.w - mu) * inv * g.w + bb.w;
    ((float4*)(out + (size_t)row * Hdim))[tid] = o4;
}

// ---------------- launch ----------------
extern "C" void kernel_launch(void* const* d_in, const int* in_sizes, int n_in,
                              void* d_out, int out_size)
{
    const float* hs     = (const float*)d_in[0];
    const float* W_in   = (const float*)d_in[1];
    const float* b_in   = (const float*)d_in[2];
    const float* conv_w = (const float*)d_in[3];
    const float* W_out  = (const float*)d_in[4];
    const float* b_out  = (const float*)d_in[5];
    const float* gamma  = (const float*)d_in[6];
    const float* beta   = (const float*)d_in[7];
    const int* maskp    = (n_in > 8) ? (const int*)d_in[8] : nullptr;
    float* out = (float*)d_out;

    void *x, *cc, *win, *wout, *y1, *y2, *wc;
    cudaGetSymbolAddress(&x, g_X);       cudaGetSymbolAddress(&cc, g_C);
    cudaGetSymbolAddress(&win, g_Win);   cudaGetSymbolAddress(&wout, g_Wout);
    cudaGetSymbolAddress(&y1, g_Y1);     cudaGetSymbolAddress(&y2, g_Y2);
    cudaGetSymbolAddress(&wc, g_Wc);

    cudaFuncSetAttribute(gemm_tf32, cudaFuncAttributeMaxDynamicSharedMemorySize, SMEM_GEMM);

    const int nAct4 = Mrows * Hdim / 4;   // 4,194,304
    const int nW4   = Hdim * Hdim / 4;    // 262,144
    round_tf32_kernel<<<4096, 256>>>((const float4*)hs, (uint4*)x, nAct4);
    round_tf32_kernel<<<512, 256>>>((const float4*)W_in, (uint4*)win, nW4);
    round_tf32_kernel<<<512, 256>>>((const float4*)W_out, (uint4*)wout, nW4);
    convw_kernel<<<1, NH>>>(conv_w, maskp, maskp ? 1 : 0, (float*)wc);

    dim3 ggrid(Hdim / 128, Mrows / 128);   // (8, 128)
    gemm_tf32<<<ggrid, 256, SMEM_GEMM>>>(
        (const float*)x, (const float*)win, b_in, nullptr, (float*)y1);

    conv_kernel<<<dim3(Hdim / 64, Sn / 128, Bn), 256>>>(
        (const float*)y1, (const float*)wc, (float*)cc);

    gemm_tf32<<<ggrid, 256, SMEM_GEMM>>>(
        (const float*)cc, (const float*)wout, b_out, hs, (float*)y2);

    ln_kernel<<<Mrows, 256>>>((const float*)y2, gamma, beta, out);
}